// round 1
// baseline (speedup 1.0000x reference)
#include <cuda_runtime.h>
#include <cstdint>

// CGC layer, fp32 exact baseline.
// Inputs (metadata order):
//   d_in[0] x  : (8192, 1024) f32
//   d_in[1] Ws : (4, 1024, 1024) f32
//   d_in[2] bs : (4, 1024) f32
//   d_in[3] Wt : (3, 4, 1024, 1024) f32
//   d_in[4] bt : (3, 4, 1024) f32
//   d_in[5] Wg : (3, 1024, 8) f32
// Output: mixture (3, 8192, 1024) f32
//
// Plan:
//   K1: gates g[t][b][e] = softmax_e(x[b] . Wg[t][:,e])        (tiny)
//   K2: y[e][b][h] = relu(x @ W_e + bias_e) for the 16 UNIQUE experts
//       (y indices 0..3 = shared experts, 4..15 = Wt[t][s] at 4 + t*4 + s)
//   K3: out[t][b][h] = sum_{j<4} g[t][b][j]   * y[4+t*4+j][b][h]
//                    + sum_{j>=4} g[t][b][j]  * y[j-4][b][h]

#define BATCH 8192
#define DM    1024
#define HD    1024
#define NTASK 3

// 16 * 8192 * 1024 floats = 512 MB scratch (static device global: allowed)
__device__ float g_y_buf[16u * BATCH * HD];
__device__ float g_gates[NTASK * BATCH * 8];

// ---------------------------------------------------------------------------
// K1: gate logits + softmax. One block per batch row, one warp per task.
// ---------------------------------------------------------------------------
__global__ __launch_bounds__(96) void gate_kernel(const float* __restrict__ x,
                                                  const float* __restrict__ Wg)
{
    const int b    = blockIdx.x;
    const int tid  = threadIdx.x;
    const int t    = tid >> 5;       // warp -> task (0..2)
    const int lane = tid & 31;

    __shared__ float xs[DM];
    for (int i = tid; i < DM; i += 96) xs[i] = x[(size_t)b * DM + i];
    __syncthreads();

    const float* Wgt = Wg + (size_t)t * DM * 8;
    float acc[8] = {0.f, 0.f, 0.f, 0.f, 0.f, 0.f, 0.f, 0.f};

    for (int d = lane; d < DM; d += 32) {
        float xv = xs[d];
        float4 w0 = *(const float4*)(Wgt + (size_t)d * 8);
        float4 w1 = *(const float4*)(Wgt + (size_t)d * 8 + 4);
        acc[0] = fmaf(xv, w0.x, acc[0]);
        acc[1] = fmaf(xv, w0.y, acc[1]);
        acc[2] = fmaf(xv, w0.z, acc[2]);
        acc[3] = fmaf(xv, w0.w, acc[3]);
        acc[4] = fmaf(xv, w1.x, acc[4]);
        acc[5] = fmaf(xv, w1.y, acc[5]);
        acc[6] = fmaf(xv, w1.z, acc[6]);
        acc[7] = fmaf(xv, w1.w, acc[7]);
    }
    #pragma unroll
    for (int off = 16; off > 0; off >>= 1) {
        #pragma unroll
        for (int j = 0; j < 8; j++)
            acc[j] += __shfl_down_sync(0xffffffffu, acc[j], off);
    }
    if (lane == 0) {
        float m = acc[0];
        #pragma unroll
        for (int j = 1; j < 8; j++) m = fmaxf(m, acc[j]);
        float e[8], s = 0.f;
        #pragma unroll
        for (int j = 0; j < 8; j++) { e[j] = expf(acc[j] - m); s += e[j]; }
        float inv = 1.f / s;
        float* gp = g_gates + ((size_t)t * BATCH + b) * 8;
        #pragma unroll
        for (int j = 0; j < 8; j++) gp[j] = e[j] * inv;
    }
}

// ---------------------------------------------------------------------------
// K2: 16 expert GEMMs, classic SGEMM 128x128x8, 256 threads, 8x8 per thread,
//     double-buffered smem, fused bias + ReLU epilogue into g_y_buf.
// ---------------------------------------------------------------------------
#define BM 128
#define BN 128
#define BK 8
#define TM 8
#define TN 8

__global__ __launch_bounds__(256) void expert_gemm(const float* __restrict__ x,
                                                   const float* __restrict__ Ws,
                                                   const float* __restrict__ bs,
                                                   const float* __restrict__ Wt,
                                                   const float* __restrict__ bt)
{
    const int e = blockIdx.z;
    const float* W;
    const float* bias;
    if (e < 4) { W = Ws + (size_t)e * DM * HD;       bias = bs + (size_t)e * HD; }
    else       { W = Wt + (size_t)(e - 4) * DM * HD; bias = bt + (size_t)(e - 4) * HD; }
    float* Y = g_y_buf + (size_t)e * BATCH * HD;

    const int m0  = blockIdx.y * BM;
    const int n0  = blockIdx.x * BN;
    const int tid = threadIdx.x;

    __shared__ float As[2][BK][BM];
    __shared__ float Bs[2][BK][BN];

    float acc[TM][TN];
    #pragma unroll
    for (int i = 0; i < TM; i++)
        #pragma unroll
        for (int j = 0; j < TN; j++) acc[i][j] = 0.f;

    // global->smem load mapping (float4)
    const int a_row = tid >> 1;          // 0..127
    const int a_col = (tid & 1) * 4;     // 0 or 4
    const int b_row = tid >> 5;          // 0..7
    const int b_col = (tid & 31) * 4;    // 0..124

    const int ty = tid >> 4;             // 0..15 -> m = ty*8
    const int tx = tid & 15;             // 0..15 -> n = tx*8

    // prologue: load k-block 0
    {
        float4 av = *(const float4*)(x + (size_t)(m0 + a_row) * DM + a_col);
        As[0][a_col + 0][a_row] = av.x;
        As[0][a_col + 1][a_row] = av.y;
        As[0][a_col + 2][a_row] = av.z;
        As[0][a_col + 3][a_row] = av.w;
        float4 bv = *(const float4*)(W + (size_t)b_row * HD + n0 + b_col);
        *(float4*)&Bs[0][b_row][b_col] = bv;
    }
    __syncthreads();

    int buf = 0;
    for (int k0 = 0; k0 < DM; k0 += BK) {
        const int nbuf = buf ^ 1;
        float4 av, bv;
        const bool has_next = (k0 + BK) < DM;
        if (has_next) {
            av = *(const float4*)(x + (size_t)(m0 + a_row) * DM + (k0 + BK) + a_col);
            bv = *(const float4*)(W + (size_t)(k0 + BK + b_row) * HD + n0 + b_col);
        }

        #pragma unroll
        for (int k = 0; k < BK; k++) {
            float a[TM], bb[TN];
            float4 a0 = *(const float4*)&As[buf][k][ty * TM];
            float4 a1 = *(const float4*)&As[buf][k][ty * TM + 4];
            a[0] = a0.x; a[1] = a0.y; a[2] = a0.z; a[3] = a0.w;
            a[4] = a1.x; a[5] = a1.y; a[6] = a1.z; a[7] = a1.w;
            float4 b0 = *(const float4*)&Bs[buf][k][tx * TN];
            float4 b1 = *(const float4*)&Bs[buf][k][tx * TN + 4];
            bb[0] = b0.x; bb[1] = b0.y; bb[2] = b0.z; bb[3] = b0.w;
            bb[4] = b1.x; bb[5] = b1.y; bb[6] = b1.z; bb[7] = b1.w;
            #pragma unroll
            for (int i = 0; i < TM; i++)
                #pragma unroll
                for (int j = 0; j < TN; j++)
                    acc[i][j] = fmaf(a[i], bb[j], acc[i][j]);
        }

        if (has_next) {
            As[nbuf][a_col + 0][a_row] = av.x;
            As[nbuf][a_col + 1][a_row] = av.y;
            As[nbuf][a_col + 2][a_row] = av.z;
            As[nbuf][a_col + 3][a_row] = av.w;
            *(float4*)&Bs[nbuf][b_row][b_col] = bv;
        }
        __syncthreads();
        buf = nbuf;
    }

    // epilogue: bias + relu, float4 stores
    float bvreg[TN];
    #pragma unroll
    for (int j = 0; j < TN; j++) bvreg[j] = bias[n0 + tx * TN + j];

    #pragma unroll
    for (int i = 0; i < TM; i++) {
        const size_t m = (size_t)(m0 + ty * TM + i);
        #pragma unroll
        for (int j = 0; j < TN; j += 4) {
            float4 r;
            r.x = fmaxf(acc[i][j + 0] + bvreg[j + 0], 0.f);
            r.y = fmaxf(acc[i][j + 1] + bvreg[j + 1], 0.f);
            r.z = fmaxf(acc[i][j + 2] + bvreg[j + 2], 0.f);
            r.w = fmaxf(acc[i][j + 3] + bvreg[j + 3], 0.f);
            *(float4*)(Y + m * HD + n0 + tx * TN + j) = r;
        }
    }
}

// ---------------------------------------------------------------------------
// K3: gated mixture. One float4 of h per thread.
// out[t][b][h] = sum_j g[t][b][j] * y[sel(t,j)][b][h]
//   j in 0..3 -> specific expert: y index 4 + t*4 + j
//   j in 4..7 -> shared expert:   y index j - 4
// ---------------------------------------------------------------------------
__global__ __launch_bounds__(256) void mix_kernel(float* __restrict__ out)
{
    const size_t idx = (size_t)blockIdx.x * blockDim.x + threadIdx.x; // over 3*8192*256
    const int h4 = (int)(idx & 255);
    const size_t tb = idx >> 8;
    const int b = (int)(tb % BATCH);
    const int t = (int)(tb / BATCH);

    const float* gp = g_gates + ((size_t)t * BATCH + b) * 8;
    float g[8];
    #pragma unroll
    for (int j = 0; j < 8; j++) g[j] = gp[j];

    float4 acc = make_float4(0.f, 0.f, 0.f, 0.f);
    #pragma unroll
    for (int j = 0; j < 8; j++) {
        const int ei = (j < 4) ? (4 + t * 4 + j) : (j - 4);
        const float4 v = *(const float4*)(g_y_buf + ((size_t)ei * BATCH + b) * HD + (size_t)h4 * 4);
        acc.x = fmaf(g[j], v.x, acc.x);
        acc.y = fmaf(g[j], v.y, acc.y);
        acc.z = fmaf(g[j], v.z, acc.z);
        acc.w = fmaf(g[j], v.w, acc.w);
    }
    *(float4*)(out + idx * 4) = acc;
}

// ---------------------------------------------------------------------------
extern "C" void kernel_launch(void* const* d_in, const int* in_sizes, int n_in,
                              void* d_out, int out_size)
{
    (void)in_sizes; (void)n_in; (void)out_size;
    const float* x  = (const float*)d_in[0];
    const float* Ws = (const float*)d_in[1];
    const float* bs = (const float*)d_in[2];
    const float* Wt = (const float*)d_in[3];
    const float* bt = (const float*)d_in[4];
    const float* Wg = (const float*)d_in[5];
    float* out = (float*)d_out;

    gate_kernel<<<BATCH, 96>>>(x, Wg);

    dim3 grid(HD / BN, BATCH / BM, 16);
    expert_gemm<<<grid, 256>>>(x, Ws, bs, Wt, bt);

    const size_t total4 = (size_t)NTASK * BATCH * (HD / 4);
    mix_kernel<<<(unsigned)(total4 / 256), 256>>>(out);
}

// round 4
// speedup vs baseline: 2.6679x; 2.6679x over previous
#include <cuda_runtime.h>
#include <cstdint>

// CGC layer — tf32 mma.sync tensor-core version (sm_100 baseline-ISA safe).
// Inputs: x(8192,1024) Ws(4,1024,1024) bs(4,1024) Wt(3,4,1024,1024) bt(3,4,1024) Wg(3,1024,8)
// Output: mixture (3, 8192, 1024) f32
//
// K1 gate:   softmax gates (unchanged)
// K2 gemm:   y[e] = relu(x @ W_e + b_e) for 16 unique experts,
//            mma.sync.m16n8k8 tf32, 128x128x32 CTA tile, cp.async double buffer
// K3 mix:    out[t][b] = sum_e gate[t][b][e] * y[sel][b]   (unchanged)

#define BATCH 8192
#define DM    1024
#define HD    1024
#define NTASK 3

__device__ float g_y_buf[16ull * BATCH * HD];   // 512 MB expert outputs
__device__ float g_gates[NTASK * BATCH * 8];

// ---------------------------------------------------------------------------
// helpers
// ---------------------------------------------------------------------------
__device__ __forceinline__ uint32_t smem_u32(const void* p) {
    uint32_t a;
    asm("{ .reg .u64 t; cvta.to.shared.u64 t, %1; cvt.u32.u64 %0, t; }" : "=r"(a) : "l"(p));
    return a;
}
__device__ __forceinline__ void cp_async16(uint32_t dst, const void* src) {
    asm volatile("cp.async.cg.shared.global [%0], [%1], 16;\n" :: "r"(dst), "l"(src) : "memory");
}
__device__ __forceinline__ void cp_commit() {
    asm volatile("cp.async.commit_group;\n" ::: "memory");
}
template <int N>
__device__ __forceinline__ void cp_wait_group() {
    asm volatile("cp.async.wait_group %0;\n" :: "n"(N) : "memory");
}
__device__ __forceinline__ uint32_t f2tf32(float f) {
    uint32_t r;
    asm("cvt.rna.tf32.f32 %0, %1;" : "=r"(r) : "f"(f));
    return r;
}
__device__ __forceinline__ void mma_tf32(float* c, const uint32_t* a, const uint32_t* b) {
    asm volatile(
        "mma.sync.aligned.m16n8k8.row.col.f32.tf32.tf32.f32 "
        "{%0,%1,%2,%3}, {%4,%5,%6,%7}, {%8,%9}, {%0,%1,%2,%3};"
        : "+f"(c[0]), "+f"(c[1]), "+f"(c[2]), "+f"(c[3])
        : "r"(a[0]), "r"(a[1]), "r"(a[2]), "r"(a[3]), "r"(b[0]), "r"(b[1]));
}

// ---------------------------------------------------------------------------
// K1: gate logits + softmax
// ---------------------------------------------------------------------------
__global__ __launch_bounds__(96) void gate_kernel(const float* __restrict__ x,
                                                  const float* __restrict__ Wg)
{
    const int b    = blockIdx.x;
    const int tid  = threadIdx.x;
    const int t    = tid >> 5;
    const int lane = tid & 31;

    __shared__ float xs[DM];
    for (int i = tid; i < DM; i += 96) xs[i] = x[(size_t)b * DM + i];
    __syncthreads();

    const float* Wgt = Wg + (size_t)t * DM * 8;
    float acc[8] = {0.f, 0.f, 0.f, 0.f, 0.f, 0.f, 0.f, 0.f};

    for (int d = lane; d < DM; d += 32) {
        float xv = xs[d];
        float4 w0 = *(const float4*)(Wgt + (size_t)d * 8);
        float4 w1 = *(const float4*)(Wgt + (size_t)d * 8 + 4);
        acc[0] = fmaf(xv, w0.x, acc[0]);
        acc[1] = fmaf(xv, w0.y, acc[1]);
        acc[2] = fmaf(xv, w0.z, acc[2]);
        acc[3] = fmaf(xv, w0.w, acc[3]);
        acc[4] = fmaf(xv, w1.x, acc[4]);
        acc[5] = fmaf(xv, w1.y, acc[5]);
        acc[6] = fmaf(xv, w1.z, acc[6]);
        acc[7] = fmaf(xv, w1.w, acc[7]);
    }
    #pragma unroll
    for (int off = 16; off > 0; off >>= 1) {
        #pragma unroll
        for (int j = 0; j < 8; j++)
            acc[j] += __shfl_down_sync(0xffffffffu, acc[j], off);
    }
    if (lane == 0) {
        float m = acc[0];
        #pragma unroll
        for (int j = 1; j < 8; j++) m = fmaxf(m, acc[j]);
        float e[8], s = 0.f;
        #pragma unroll
        for (int j = 0; j < 8; j++) { e[j] = expf(acc[j] - m); s += e[j]; }
        float inv = 1.f / s;
        float* gp = g_gates + ((size_t)t * BATCH + b) * 8;
        #pragma unroll
        for (int j = 0; j < 8; j++) gp[j] = e[j] * inv;
    }
}

// ---------------------------------------------------------------------------
// K2: tf32 mma.sync expert GEMM.
// CTA tile 128(M) x 128(N) x 32(K); 8 warps in 2x4 -> 64x32 warp tiles.
// A smem [128][36] (pad 4), B smem [32][136] (pad 8), double-buffered.
// ---------------------------------------------------------------------------
#define AS_STRIDE 36
#define BS_STRIDE 136
#define AS_BYTES  (128 * AS_STRIDE * 4)   // 18432
#define BS_BYTES  (32 * BS_STRIDE * 4)    // 17408
#define SMEM_GEMM (2 * AS_BYTES + 2 * BS_BYTES + 512)

__global__ __launch_bounds__(256, 2) void expert_gemm_mma(const float* __restrict__ x,
                                                          const float* __restrict__ Ws,
                                                          const float* __restrict__ bs,
                                                          const float* __restrict__ Wt,
                                                          const float* __restrict__ bt)
{
    extern __shared__ char smem[];
    float* As[2] = { (float*)smem, (float*)(smem + AS_BYTES) };
    float* Bs[2] = { (float*)(smem + 2 * AS_BYTES), (float*)(smem + 2 * AS_BYTES + BS_BYTES) };
    float* biassm = (float*)(smem + 2 * AS_BYTES + 2 * BS_BYTES);
    const uint32_t sbase = smem_u32(smem);
    const uint32_t as_u32[2] = { sbase, sbase + AS_BYTES };
    const uint32_t bs_u32[2] = { sbase + 2 * AS_BYTES, sbase + 2 * AS_BYTES + BS_BYTES };

    const int tid  = threadIdx.x;
    const int w    = tid >> 5;
    const int lane = tid & 31;
    const int gid  = lane >> 2;     // 0..7
    const int tig  = lane & 3;      // 0..3
    const int warp_m = (w >> 2) * 64;   // 0 or 64
    const int warp_n = (w & 3) * 32;    // 0,32,64,96

    const int e  = blockIdx.z;
    const int n0 = blockIdx.x * 128;
    const int m0 = blockIdx.y * 128;

    const float* W    = (e < 4) ? Ws + (size_t)e * DM * HD : Wt + (size_t)(e - 4) * DM * HD;
    const float* bias = (e < 4) ? bs + (size_t)e * HD      : bt + (size_t)(e - 4) * HD;
    float* Y = g_y_buf + (size_t)e * BATCH * HD;

    if (tid < 128) biassm[tid] = bias[n0 + tid];

    float c[2][4][4];
    #pragma unroll
    for (int mi = 0; mi < 2; mi++)
        #pragma unroll
        for (int ni = 0; ni < 4; ni++)
            #pragma unroll
            for (int r = 0; r < 4; r++) c[mi][ni][r] = 0.f;

    // ---- async stage loader: A 128x32, B 32x128 (both fp32, float4 chunks)
    auto load_stage = [&](int s, int kt) {
        const int kbase = kt * 32;
        #pragma unroll
        for (int i = 0; i < 4; i++) {
            const int idx = tid + i * 256;        // 0..1023
            const int row = idx >> 3, q = idx & 7;
            cp_async16(as_u32[s] + (uint32_t)(row * AS_STRIDE + q * 4) * 4,
                       x + (size_t)(m0 + row) * DM + kbase + q * 4);
        }
        #pragma unroll
        for (int i = 0; i < 4; i++) {
            const int idx = tid + i * 256;
            const int row = idx >> 5, q = idx & 31;
            cp_async16(bs_u32[s] + (uint32_t)(row * BS_STRIDE + q * 4) * 4,
                       W + (size_t)(kbase + row) * HD + n0 + q * 4);
        }
        cp_commit();
    };

    load_stage(0, 0);
    int buf = 0;

    for (int kt = 0; kt < 32; kt++) {
        if (kt < 31) { load_stage(buf ^ 1, kt + 1); cp_wait_group<1>(); }
        else         { cp_wait_group<0>(); }
        __syncthreads();

        const float* Asb = As[buf];
        const float* Bsb = Bs[buf];

        #pragma unroll
        for (int ks = 0; ks < 4; ks++) {
            const int k = ks * 8;
            // A fragments: 2 m-tiles of 32 rows -> 2 frag-pairs... warp tile 64 rows = 4 x 16
            uint32_t a[4][4];
            #pragma unroll
            for (int mi = 0; mi < 4; mi++) {
                const int m = warp_m + mi * 16;
                a[mi][0] = f2tf32(Asb[(m + gid)     * AS_STRIDE + k + tig]);
                a[mi][1] = f2tf32(Asb[(m + gid + 8) * AS_STRIDE + k + tig]);
                a[mi][2] = f2tf32(Asb[(m + gid)     * AS_STRIDE + k + tig + 4]);
                a[mi][3] = f2tf32(Asb[(m + gid + 8) * AS_STRIDE + k + tig + 4]);
            }
            uint32_t b[4][2];
            #pragma unroll
            for (int ni = 0; ni < 4; ni++) {
                const int n = warp_n + ni * 8;
                b[ni][0] = f2tf32(Bsb[(k + tig)     * BS_STRIDE + n + gid]);
                b[ni][1] = f2tf32(Bsb[(k + tig + 4) * BS_STRIDE + n + gid]);
            }
            // 64x32 warp tile: c indexed [mi/2 groups of 2][ni]
            #pragma unroll
            for (int mi = 0; mi < 4; mi++)
                #pragma unroll
                for (int ni = 0; ni < 4; ni++)
                    mma_tf32(&c[mi >> 1][ni][(mi & 1) ? 0 : 0] + 0, a[mi], b[ni]);
            // NOTE: accumulate layout handled below — see c2 mapping
        }
        __syncthreads();
        buf ^= 1;
    }

    // ------- epilogue (c mapping: see loop above) -------
    // The mma loop above writes c[mi>>1][ni] for mi 0..3 — but two mi share a slot.
    // To keep 64 accum floats we fold mi into the row offset at store time via
    // the identity used in the loop: mi pairs (0,1)->slot0 rows +0/+16, (2,3)->slot1.
    // (Handled by using 4 distinct slots: c[][] is [2][4][4] with mi>>1 and the
    //  mi&1 row offset folded into the fragment row — accumulators for mi&1==1
    //  live in the SAME slot, which would be WRONG; instead we use mi&1 to pick
    //  between the two row-halves stored in c[mi>>1][ni]: rows gid / gid+8 map to
    //  (c0,c1)/(c2,c3), and mi&1 selects +0 / +16 handled in the mma above.)
    // --- Correct, simple version: re-declare as 4 slots ---
    (void)0;

    // store
    #pragma unroll
    for (int mi = 0; mi < 2; mi++) {
        #pragma unroll
        for (int ni = 0; ni < 4; ni++) {
            const int rbase = m0 + warp_m + mi * 32 + gid;
            const int col   = warp_n + ni * 8 + 2 * tig;
            const float b0 = biassm[col], b1 = biassm[col + 1];
            float2 v0, v1;
            v0.x = fmaxf(c[mi][ni][0] + b0, 0.f);
            v0.y = fmaxf(c[mi][ni][1] + b1, 0.f);
            v1.x = fmaxf(c[mi][ni][2] + b0, 0.f);
            v1.y = fmaxf(c[mi][ni][3] + b1, 0.f);
            *(float2*)(Y + (size_t)rbase * HD + n0 + col)       = v0;
            *(float2*)(Y + (size_t)(rbase + 8) * HD + n0 + col) = v1;
        }
    }
}

// The warp tile above is 64x32 but with only [2][4] accumulator slots we cover
// 32x32 per slot-pair => the mi loop must match the slots. Fix: use m32 tiles,
// i.e. mi in {0,1} covering rows warp_m + mi*32 with m16n8k8 applied twice per
// slot (rows +0..15 via frag rows gid/gid+8, and +16..31 needs its own slot).
// To keep this file correct and registers bounded, the kernel is compiled with
// WARP_M = 32: 8 warps in 4x2 layout covering 128x128? 4*32=128 rows, 2*64...
// -- resolved below by a second corrected kernel actually used at launch. --

#define AS2 AS_STRIDE
#define BS2 BS_STRIDE

__global__ __launch_bounds__(256, 2) void expert_gemm_mma2(const float* __restrict__ x,
                                                           const float* __restrict__ Ws,
                                                           const float* __restrict__ bs,
                                                           const float* __restrict__ Wt,
                                                           const float* __restrict__ bt)
{
    extern __shared__ char smem[];
    float* As[2] = { (float*)smem, (float*)(smem + AS_BYTES) };
    float* Bs[2] = { (float*)(smem + 2 * AS_BYTES), (float*)(smem + 2 * AS_BYTES + BS_BYTES) };
    float* biassm = (float*)(smem + 2 * AS_BYTES + 2 * BS_BYTES);
    const uint32_t sbase = smem_u32(smem);
    const uint32_t as_u32[2] = { sbase, sbase + AS_BYTES };
    const uint32_t bs_u32[2] = { sbase + 2 * AS_BYTES, sbase + 2 * AS_BYTES + BS_BYTES };

    const int tid  = threadIdx.x;
    const int w    = tid >> 5;
    const int lane = tid & 31;
    const int gid  = lane >> 2;
    const int tig  = lane & 3;
    // 8 warps: 2 (m) x 4 (n); warp tile 64 (m) x 32 (n)
    const int warp_m = (w >> 2) * 64;
    const int warp_n = (w & 3) * 32;

    const int e  = blockIdx.z;
    const int n0 = blockIdx.x * 128;
    const int m0 = blockIdx.y * 128;

    const float* W    = (e < 4) ? Ws + (size_t)e * DM * HD : Wt + (size_t)(e - 4) * DM * HD;
    const float* bias = (e < 4) ? bs + (size_t)e * HD      : bt + (size_t)(e - 4) * HD;
    float* Y = g_y_buf + (size_t)e * BATCH * HD;

    if (tid < 128) biassm[tid] = bias[n0 + tid];

    // accumulators: 4 m-frags (16 rows) x 4 n-frags (8 cols) x 4 regs = 64 floats
    float c[4][4][4];
    #pragma unroll
    for (int mi = 0; mi < 4; mi++)
        #pragma unroll
        for (int ni = 0; ni < 4; ni++)
            #pragma unroll
            for (int r = 0; r < 4; r++) c[mi][ni][r] = 0.f;

    auto load_stage = [&](int s, int kt) {
        const int kbase = kt * 32;
        #pragma unroll
        for (int i = 0; i < 4; i++) {
            const int idx = tid + i * 256;
            const int row = idx >> 3, q = idx & 7;
            cp_async16(as_u32[s] + (uint32_t)(row * AS2 + q * 4) * 4,
                       x + (size_t)(m0 + row) * DM + kbase + q * 4);
        }
        #pragma unroll
        for (int i = 0; i < 4; i++) {
            const int idx = tid + i * 256;
            const int row = idx >> 5, q = idx & 31;
            cp_async16(bs_u32[s] + (uint32_t)(row * BS2 + q * 4) * 4,
                       W + (size_t)(kbase + row) * HD + n0 + q * 4);
        }
        cp_commit();
    };

    load_stage(0, 0);
    int buf = 0;

    for (int kt = 0; kt < 32; kt++) {
        if (kt < 31) { load_stage(buf ^ 1, kt + 1); cp_wait_group<1>(); }
        else         { cp_wait_group<0>(); }
        __syncthreads();

        const float* Asb = As[buf];
        const float* Bsb = Bs[buf];

        #pragma unroll
        for (int ks = 0; ks < 4; ks++) {
            const int k = ks * 8;
            uint32_t a[4][4];
            #pragma unroll
            for (int mi = 0; mi < 4; mi++) {
                const int m = warp_m + mi * 16;
                a[mi][0] = f2tf32(Asb[(m + gid)     * AS2 + k + tig]);
                a[mi][1] = f2tf32(Asb[(m + gid + 8) * AS2 + k + tig]);
                a[mi][2] = f2tf32(Asb[(m + gid)     * AS2 + k + tig + 4]);
                a[mi][3] = f2tf32(Asb[(m + gid + 8) * AS2 + k + tig + 4]);
            }
            uint32_t b[4][2];
            #pragma unroll
            for (int ni = 0; ni < 4; ni++) {
                const int n = warp_n + ni * 8;
                b[ni][0] = f2tf32(Bsb[(k + tig)     * BS2 + n + gid]);
                b[ni][1] = f2tf32(Bsb[(k + tig + 4) * BS2 + n + gid]);
            }
            #pragma unroll
            for (int mi = 0; mi < 4; mi++)
                #pragma unroll
                for (int ni = 0; ni < 4; ni++)
                    mma_tf32(c[mi][ni], a[mi], b[ni]);
        }
        __syncthreads();
        buf ^= 1;
    }

    // epilogue: bias + relu, float2 stores
    #pragma unroll
    for (int mi = 0; mi < 4; mi++) {
        #pragma unroll
        for (int ni = 0; ni < 4; ni++) {
            const int rbase = m0 + warp_m + mi * 16 + gid;
            const int col   = warp_n + ni * 8 + 2 * tig;
            const float b0 = biassm[col], b1 = biassm[col + 1];
            float2 v0, v1;
            v0.x = fmaxf(c[mi][ni][0] + b0, 0.f);
            v0.y = fmaxf(c[mi][ni][1] + b1, 0.f);
            v1.x = fmaxf(c[mi][ni][2] + b0, 0.f);
            v1.y = fmaxf(c[mi][ni][3] + b1, 0.f);
            *(float2*)(Y + (size_t)rbase * HD + n0 + col)       = v0;
            *(float2*)(Y + (size_t)(rbase + 8) * HD + n0 + col) = v1;
        }
    }
}

// ---------------------------------------------------------------------------
// K3: gated mixture
// ---------------------------------------------------------------------------
__global__ __launch_bounds__(256) void mix_kernel(float* __restrict__ out)
{
    const size_t idx = (size_t)blockIdx.x * blockDim.x + threadIdx.x;
    const int h4 = (int)(idx & 255);
    const size_t tb = idx >> 8;
    const int b = (int)(tb % BATCH);
    const int t = (int)(tb / BATCH);

    const float* gp = g_gates + ((size_t)t * BATCH + b) * 8;
    float g[8];
    #pragma unroll
    for (int j = 0; j < 8; j++) g[j] = gp[j];

    float4 acc = make_float4(0.f, 0.f, 0.f, 0.f);
    #pragma unroll
    for (int j = 0; j < 8; j++) {
        const int ei = (j < 4) ? (4 + t * 4 + j) : (j - 4);
        const float4 v = *(const float4*)(g_y_buf + ((size_t)ei * BATCH + b) * HD + (size_t)h4 * 4);
        acc.x = fmaf(g[j], v.x, acc.x);
        acc.y = fmaf(g[j], v.y, acc.y);
        acc.z = fmaf(g[j], v.z, acc.z);
        acc.w = fmaf(g[j], v.w, acc.w);
    }
    *(float4*)(out + idx * 4) = acc;
}

// ---------------------------------------------------------------------------
extern "C" void kernel_launch(void* const* d_in, const int* in_sizes, int n_in,
                              void* d_out, int out_size)
{
    (void)in_sizes; (void)n_in; (void)out_size;
    const float* x  = (const float*)d_in[0];
    const float* Ws = (const float*)d_in[1];
    const float* bs = (const float*)d_in[2];
    const float* Wt = (const float*)d_in[3];
    const float* bt = (const float*)d_in[4];
    const float* Wg = (const float*)d_in[5];
    float* out = (float*)d_out;

    cudaFuncSetAttribute(expert_gemm_mma2,
                         cudaFuncAttributeMaxDynamicSharedMemorySize, SMEM_GEMM);

    gate_kernel<<<BATCH, 96>>>(x, Wg);
    expert_gemm_mma2<<<dim3(8, 64, 16), 256, SMEM_GEMM>>>(x, Ws, bs, Wt, bt);

    const size_t total4 = (size_t)NTASK * BATCH * (HD / 4);
    mix_kernel<<<(unsigned)(total4 / 256), 256>>>(out);
}

// round 5
// speedup vs baseline: 3.2648x; 1.2237x over previous
#include <cuda_runtime.h>
#include <cstdint>

// CGC layer — tf32 mma.sync v2: pre-converted operands, 64x64 warp tiles,
// 3-stage cp.async pipeline.
// Inputs: x(8192,1024) Ws(4,1024,1024) bs(4,1024) Wt(3,4,1024,1024) bt(3,4,1024) Wg(3,1024,8)
// Output: mixture (3, 8192, 1024) f32

#define BATCH 8192
#define DM    1024
#define HD    1024
#define NTASK 3

__device__ float g_y_buf[16ull * BATCH * HD];   // 512 MB expert outputs
__device__ float g_gates[NTASK * BATCH * 8];
__device__ float g_xc[(size_t)BATCH * DM];      // 32 MB x, tf32-rounded
__device__ float g_wc[16ull * DM * HD];         // 64 MB W, tf32-rounded

// ---------------------------------------------------------------------------
// helpers
// ---------------------------------------------------------------------------
__device__ __forceinline__ uint32_t smem_u32(const void* p) {
    uint32_t a;
    asm("{ .reg .u64 t; cvta.to.shared.u64 t, %1; cvt.u32.u64 %0, t; }" : "=r"(a) : "l"(p));
    return a;
}
__device__ __forceinline__ void cp_async16(uint32_t dst, const void* src) {
    asm volatile("cp.async.cg.shared.global [%0], [%1], 16;\n" :: "r"(dst), "l"(src) : "memory");
}
__device__ __forceinline__ void cp_commit() {
    asm volatile("cp.async.commit_group;\n" ::: "memory");
}
template <int N>
__device__ __forceinline__ void cp_wait_group() {
    asm volatile("cp.async.wait_group %0;\n" :: "n"(N) : "memory");
}
__device__ __forceinline__ float f2tf32f(float f) {
    uint32_t r;
    asm("cvt.rna.tf32.f32 %0, %1;" : "=r"(r) : "f"(f));
    return __uint_as_float(r);
}
__device__ __forceinline__ void mma_tf32(float* c, const uint32_t* a, const uint32_t* b) {
    asm volatile(
        "mma.sync.aligned.m16n8k8.row.col.f32.tf32.tf32.f32 "
        "{%0,%1,%2,%3}, {%4,%5,%6,%7}, {%8,%9}, {%0,%1,%2,%3};"
        : "+f"(c[0]), "+f"(c[1]), "+f"(c[2]), "+f"(c[3])
        : "r"(a[0]), "r"(a[1]), "r"(a[2]), "r"(a[3]), "r"(b[0]), "r"(b[1]));
}

// ---------------------------------------------------------------------------
// K0: tf32 pre-round (generic, float4)
// ---------------------------------------------------------------------------
__global__ __launch_bounds__(256) void cvt_kernel(const float* __restrict__ src,
                                                  float* __restrict__ dst)
{
    const size_t i = ((size_t)blockIdx.x * blockDim.x + threadIdx.x) * 4;
    float4 v = *(const float4*)(src + i);
    v.x = f2tf32f(v.x);
    v.y = f2tf32f(v.y);
    v.z = f2tf32f(v.z);
    v.w = f2tf32f(v.w);
    *(float4*)(dst + i) = v;
}

// ---------------------------------------------------------------------------
// K1: gate logits + softmax
// ---------------------------------------------------------------------------
__global__ __launch_bounds__(96) void gate_kernel(const float* __restrict__ x,
                                                  const float* __restrict__ Wg)
{
    const int b    = blockIdx.x;
    const int tid  = threadIdx.x;
    const int t    = tid >> 5;
    const int lane = tid & 31;

    __shared__ float xs[DM];
    for (int i = tid; i < DM; i += 96) xs[i] = x[(size_t)b * DM + i];
    __syncthreads();

    const float* Wgt = Wg + (size_t)t * DM * 8;
    float acc[8] = {0.f, 0.f, 0.f, 0.f, 0.f, 0.f, 0.f, 0.f};

    for (int d = lane; d < DM; d += 32) {
        float xv = xs[d];
        float4 w0 = *(const float4*)(Wgt + (size_t)d * 8);
        float4 w1 = *(const float4*)(Wgt + (size_t)d * 8 + 4);
        acc[0] = fmaf(xv, w0.x, acc[0]);
        acc[1] = fmaf(xv, w0.y, acc[1]);
        acc[2] = fmaf(xv, w0.z, acc[2]);
        acc[3] = fmaf(xv, w0.w, acc[3]);
        acc[4] = fmaf(xv, w1.x, acc[4]);
        acc[5] = fmaf(xv, w1.y, acc[5]);
        acc[6] = fmaf(xv, w1.z, acc[6]);
        acc[7] = fmaf(xv, w1.w, acc[7]);
    }
    #pragma unroll
    for (int off = 16; off > 0; off >>= 1) {
        #pragma unroll
        for (int j = 0; j < 8; j++)
            acc[j] += __shfl_down_sync(0xffffffffu, acc[j], off);
    }
    if (lane == 0) {
        float m = acc[0];
        #pragma unroll
        for (int j = 1; j < 8; j++) m = fmaxf(m, acc[j]);
        float e[8], s = 0.f;
        #pragma unroll
        for (int j = 0; j < 8; j++) { e[j] = expf(acc[j] - m); s += e[j]; }
        float inv = 1.f / s;
        float* gp = g_gates + ((size_t)t * BATCH + b) * 8;
        #pragma unroll
        for (int j = 0; j < 8; j++) gp[j] = e[j] * inv;
    }
}

// ---------------------------------------------------------------------------
// K2: tf32 mma.sync expert GEMM v2.
// CTA tile 256(M) x 128(N) x 32(K); 8 warps 4(m)x2(n) -> 64x64 warp tiles.
// A smem [256][36], B smem [32][136], 3-stage cp.async pipeline.
// Operands pre-rounded to tf32 -> no cvt in mainloop.
// ---------------------------------------------------------------------------
#define STAGES    3
#define AS_STRIDE 36
#define BS_STRIDE 136
#define AS_BYTES  (256 * AS_STRIDE * 4)   // 36864
#define BS_BYTES  (32 * BS_STRIDE * 4)    // 17408
#define STAGE_BYTES (AS_BYTES + BS_BYTES) // 54272
#define SMEM_GEMM (STAGES * STAGE_BYTES + 512)

__global__ __launch_bounds__(256, 1) void expert_gemm_mma3(const float* __restrict__ bs,
                                                           const float* __restrict__ bt)
{
    extern __shared__ char smem[];
    const uint32_t sbase = smem_u32(smem);
    float* biassm = (float*)(smem + STAGES * STAGE_BYTES);

    const int tid  = threadIdx.x;
    const int w    = tid >> 5;
    const int lane = tid & 31;
    const int gid  = lane >> 2;     // 0..7
    const int tig  = lane & 3;      // 0..3
    const int warp_m = (w >> 1) * 64;   // 0,64,128,192
    const int warp_n = (w & 1) * 64;    // 0,64

    const int e  = blockIdx.z;
    const int n0 = blockIdx.x * 128;
    const int m0 = blockIdx.y * 256;

    const float* W    = g_wc + (size_t)e * DM * HD;
    const float* bias = (e < 4) ? bs + (size_t)e * HD : bt + (size_t)(e - 4) * HD;
    float* Y = g_y_buf + (size_t)e * BATCH * HD;

    if (tid < 128) biassm[tid] = bias[n0 + tid];

    // accumulators: 4 m-frags x 8 n-frags x 4 = 128 floats
    float c[4][8][4];
    #pragma unroll
    for (int mi = 0; mi < 4; mi++)
        #pragma unroll
        for (int ni = 0; ni < 8; ni++)
            #pragma unroll
            for (int r = 0; r < 4; r++) c[mi][ni][r] = 0.f;

    auto load_stage = [&](int s, int kt) {
        const uint32_t ab = sbase + (uint32_t)s * STAGE_BYTES;
        const uint32_t bb = ab + AS_BYTES;
        const int kbase = kt * 32;
        #pragma unroll
        for (int i = 0; i < 8; i++) {               // A: 256x32 = 2048 float4
            const int idx = tid + i * 256;
            const int row = idx >> 3, q = idx & 7;
            cp_async16(ab + (uint32_t)(row * AS_STRIDE + q * 4) * 4,
                       g_xc + (size_t)(m0 + row) * DM + kbase + q * 4);
        }
        #pragma unroll
        for (int i = 0; i < 4; i++) {               // B: 32x128 = 1024 float4
            const int idx = tid + i * 256;
            const int row = idx >> 5, q = idx & 31;
            cp_async16(bb + (uint32_t)(row * BS_STRIDE + q * 4) * 4,
                       W + (size_t)(kbase + row) * HD + n0 + q * 4);
        }
        cp_commit();
    };

    load_stage(0, 0);
    load_stage(1, 1);

    for (int kt = 0; kt < 32; kt++) {
        __syncthreads();                         // stage (kt-1)%3 free for reuse
        if (kt + 2 < 32) { load_stage((kt + 2) % STAGES, kt + 2); cp_wait_group<2>(); }
        else if (kt + 1 < 32) { cp_wait_group<1>(); }
        else { cp_wait_group<0>(); }
        __syncthreads();                         // stage kt visible to all warps

        const float* Asb = (const float*)(smem + (kt % STAGES) * STAGE_BYTES);
        const float* Bsb = (const float*)(smem + (kt % STAGES) * STAGE_BYTES + AS_BYTES);

        #pragma unroll
        for (int ks = 0; ks < 4; ks++) {
            const int k = ks * 8;
            uint32_t a[4][4];
            #pragma unroll
            for (int mi = 0; mi < 4; mi++) {
                const int m = warp_m + mi * 16;
                a[mi][0] = __float_as_uint(Asb[(m + gid)     * AS_STRIDE + k + tig]);
                a[mi][1] = __float_as_uint(Asb[(m + gid + 8) * AS_STRIDE + k + tig]);
                a[mi][2] = __float_as_uint(Asb[(m + gid)     * AS_STRIDE + k + tig + 4]);
                a[mi][3] = __float_as_uint(Asb[(m + gid + 8) * AS_STRIDE + k + tig + 4]);
            }
            uint32_t b[8][2];
            #pragma unroll
            for (int ni = 0; ni < 8; ni++) {
                const int n = warp_n + ni * 8;
                b[ni][0] = __float_as_uint(Bsb[(k + tig)     * BS_STRIDE + n + gid]);
                b[ni][1] = __float_as_uint(Bsb[(k + tig + 4) * BS_STRIDE + n + gid]);
            }
            #pragma unroll
            for (int mi = 0; mi < 4; mi++)
                #pragma unroll
                for (int ni = 0; ni < 8; ni++)
                    mma_tf32(c[mi][ni], a[mi], b[ni]);
        }
    }

    // epilogue: bias + relu, float2 stores
    #pragma unroll
    for (int mi = 0; mi < 4; mi++) {
        #pragma unroll
        for (int ni = 0; ni < 8; ni++) {
            const int rbase = m0 + warp_m + mi * 16 + gid;
            const int col   = warp_n + ni * 8 + 2 * tig;
            const float b0 = biassm[col], b1 = biassm[col + 1];
            float2 v0, v1;
            v0.x = fmaxf(c[mi][ni][0] + b0, 0.f);
            v0.y = fmaxf(c[mi][ni][1] + b1, 0.f);
            v1.x = fmaxf(c[mi][ni][2] + b0, 0.f);
            v1.y = fmaxf(c[mi][ni][3] + b1, 0.f);
            *(float2*)(Y + (size_t)rbase * HD + n0 + col)       = v0;
            *(float2*)(Y + (size_t)(rbase + 8) * HD + n0 + col) = v1;
        }
    }
}

// ---------------------------------------------------------------------------
// K3: gated mixture
// ---------------------------------------------------------------------------
__global__ __launch_bounds__(256) void mix_kernel(float* __restrict__ out)
{
    const size_t idx = (size_t)blockIdx.x * blockDim.x + threadIdx.x;
    const int h4 = (int)(idx & 255);
    const size_t tb = idx >> 8;
    const int b = (int)(tb % BATCH);
    const int t = (int)(tb / BATCH);

    const float* gp = g_gates + ((size_t)t * BATCH + b) * 8;
    float g[8];
    #pragma unroll
    for (int j = 0; j < 8; j++) g[j] = gp[j];

    float4 acc = make_float4(0.f, 0.f, 0.f, 0.f);
    #pragma unroll
    for (int j = 0; j < 8; j++) {
        const int ei = (j < 4) ? (4 + t * 4 + j) : (j - 4);
        const float4 v = *(const float4*)(g_y_buf + ((size_t)ei * BATCH + b) * HD + (size_t)h4 * 4);
        acc.x = fmaf(g[j], v.x, acc.x);
        acc.y = fmaf(g[j], v.y, acc.y);
        acc.z = fmaf(g[j], v.z, acc.z);
        acc.w = fmaf(g[j], v.w, acc.w);
    }
    *(float4*)(out + idx * 4) = acc;
}

// ---------------------------------------------------------------------------
extern "C" void kernel_launch(void* const* d_in, const int* in_sizes, int n_in,
                              void* d_out, int out_size)
{
    (void)in_sizes; (void)n_in; (void)out_size;
    const float* x  = (const float*)d_in[0];
    const float* Ws = (const float*)d_in[1];
    const float* bs = (const float*)d_in[2];
    const float* Wt = (const float*)d_in[3];
    const float* bt = (const float*)d_in[4];
    const float* Wg = (const float*)d_in[5];
    float* out = (float*)d_out;

    cudaFuncSetAttribute(expert_gemm_mma3,
                         cudaFuncAttributeMaxDynamicSharedMemorySize, SMEM_GEMM);

    // pre-round operands to tf32
    {
        float* xc = nullptr; float* wc = nullptr;
        cudaGetSymbolAddress((void**)&xc, g_xc);
        cudaGetSymbolAddress((void**)&wc, g_wc);
        cvt_kernel<<<(unsigned)((size_t)BATCH * DM / 4 / 256), 256>>>(x, xc);
        cvt_kernel<<<(unsigned)(4ull * DM * HD / 4 / 256), 256>>>(Ws, wc);
        cvt_kernel<<<(unsigned)(12ull * DM * HD / 4 / 256), 256>>>(Wt, wc + 4ull * DM * HD);
    }

    gate_kernel<<<BATCH, 96>>>(x, Wg);
    expert_gemm_mma3<<<dim3(8, 32, 16), 256, SMEM_GEMM>>>(bs, bt);

    const size_t total4 = (size_t)NTASK * BATCH * (HD / 4);
    mix_kernel<<<(unsigned)(total4 / 256), 256>>>(out);
}

// round 6
// speedup vs baseline: 4.9124x; 1.5047x over previous
#include <cuda_runtime.h>
#include <cuda_fp16.h>
#include <cstdint>

// CGC layer — fp16 mma.sync m16n8k16 (fp32 accumulate).
// fp16 and tf32 share an 11-bit significand; data range fits fp16 easily,
// so precision matches the tf32 version (~1.7e-4) at 2x FLOP/instruction.
// Inputs: x(8192,1024) Ws(4,1024,1024) bs(4,1024) Wt(3,4,1024,1024) bt(3,4,1024) Wg(3,1024,8)
// Output: mixture (3, 8192, 1024) f32

#define BATCH 8192
#define DM    1024
#define HD    1024
#define NTASK 3

__device__ float  g_y_buf[16ull * BATCH * HD];     // 512 MB expert outputs
__device__ float  g_gates[NTASK * BATCH * 8];
__device__ __half g_xh[(size_t)BATCH * DM];        // 16 MB x fp16 [b][k]
__device__ __half g_wh[16ull * DM * HD];           // 32 MB W fp16 transposed [e][n][k]

// ---------------------------------------------------------------------------
// helpers
// ---------------------------------------------------------------------------
__device__ __forceinline__ uint32_t smem_u32(const void* p) {
    uint32_t a;
    asm("{ .reg .u64 t; cvta.to.shared.u64 t, %1; cvt.u32.u64 %0, t; }" : "=r"(a) : "l"(p));
    return a;
}
__device__ __forceinline__ void cp_async16(uint32_t dst, const void* src) {
    asm volatile("cp.async.cg.shared.global [%0], [%1], 16;\n" :: "r"(dst), "l"(src) : "memory");
}
__device__ __forceinline__ void cp_commit() {
    asm volatile("cp.async.commit_group;\n" ::: "memory");
}
template <int N>
__device__ __forceinline__ void cp_wait_group() {
    asm volatile("cp.async.wait_group %0;\n" :: "n"(N) : "memory");
}
__device__ __forceinline__ void mma_f16(float* c, const uint32_t* a, const uint32_t* b) {
    asm volatile(
        "mma.sync.aligned.m16n8k16.row.col.f32.f16.f16.f32 "
        "{%0,%1,%2,%3}, {%4,%5,%6,%7}, {%8,%9}, {%0,%1,%2,%3};"
        : "+f"(c[0]), "+f"(c[1]), "+f"(c[2]), "+f"(c[3])
        : "r"(a[0]), "r"(a[1]), "r"(a[2]), "r"(a[3]), "r"(b[0]), "r"(b[1]));
}

// ---------------------------------------------------------------------------
// K0a: x fp32 -> fp16 (straight copy layout)
// ---------------------------------------------------------------------------
__global__ __launch_bounds__(256) void cvt_x(const float* __restrict__ src,
                                             __half* __restrict__ dst)
{
    const size_t i = ((size_t)blockIdx.x * blockDim.x + threadIdx.x) * 8;
    float4 v0 = *(const float4*)(src + i);
    float4 v1 = *(const float4*)(src + i + 4);
    __half2 h[4];
    h[0] = __floats2half2_rn(v0.x, v0.y);
    h[1] = __floats2half2_rn(v0.z, v0.w);
    h[2] = __floats2half2_rn(v1.x, v1.y);
    h[3] = __floats2half2_rn(v1.z, v1.w);
    *(uint4*)(dst + i) = *(uint4*)h;
}

// ---------------------------------------------------------------------------
// K0b: W fp32 [e][k][n] -> fp16 transposed [e][n][k]
// ---------------------------------------------------------------------------
__global__ __launch_bounds__(256) void cvt_w(const float* __restrict__ Ws,
                                             const float* __restrict__ Wt)
{
    __shared__ float t[32][33];
    const int e = blockIdx.z;
    const float* src = (e < 4) ? Ws + (size_t)e * DM * HD
                               : Wt + (size_t)(e - 4) * DM * HD;
    const int n0 = blockIdx.x * 32;
    const int k0 = blockIdx.y * 32;
    const int tx = threadIdx.x & 31;
    const int ty = threadIdx.x >> 5;   // 0..7

    #pragma unroll
    for (int i = 0; i < 32; i += 8)
        t[ty + i][tx] = src[(size_t)(k0 + ty + i) * HD + n0 + tx];
    __syncthreads();
    __half* dst = g_wh + (size_t)e * DM * HD;
    #pragma unroll
    for (int i = 0; i < 32; i += 8)
        dst[(size_t)(n0 + ty + i) * DM + k0 + tx] = __float2half_rn(t[tx][ty + i]);
}

// ---------------------------------------------------------------------------
// K1: gate logits + softmax (fp32, unchanged)
// ---------------------------------------------------------------------------
__global__ __launch_bounds__(96) void gate_kernel(const float* __restrict__ x,
                                                  const float* __restrict__ Wg)
{
    const int b    = blockIdx.x;
    const int tid  = threadIdx.x;
    const int t    = tid >> 5;
    const int lane = tid & 31;

    __shared__ float xs[DM];
    for (int i = tid; i < DM; i += 96) xs[i] = x[(size_t)b * DM + i];
    __syncthreads();

    const float* Wgt = Wg + (size_t)t * DM * 8;
    float acc[8] = {0.f, 0.f, 0.f, 0.f, 0.f, 0.f, 0.f, 0.f};

    for (int d = lane; d < DM; d += 32) {
        float xv = xs[d];
        float4 w0 = *(const float4*)(Wgt + (size_t)d * 8);
        float4 w1 = *(const float4*)(Wgt + (size_t)d * 8 + 4);
        acc[0] = fmaf(xv, w0.x, acc[0]);
        acc[1] = fmaf(xv, w0.y, acc[1]);
        acc[2] = fmaf(xv, w0.z, acc[2]);
        acc[3] = fmaf(xv, w0.w, acc[3]);
        acc[4] = fmaf(xv, w1.x, acc[4]);
        acc[5] = fmaf(xv, w1.y, acc[5]);
        acc[6] = fmaf(xv, w1.z, acc[6]);
        acc[7] = fmaf(xv, w1.w, acc[7]);
    }
    #pragma unroll
    for (int off = 16; off > 0; off >>= 1) {
        #pragma unroll
        for (int j = 0; j < 8; j++)
            acc[j] += __shfl_down_sync(0xffffffffu, acc[j], off);
    }
    if (lane == 0) {
        float m = acc[0];
        #pragma unroll
        for (int j = 1; j < 8; j++) m = fmaxf(m, acc[j]);
        float e[8], s = 0.f;
        #pragma unroll
        for (int j = 0; j < 8; j++) { e[j] = expf(acc[j] - m); s += e[j]; }
        float inv = 1.f / s;
        float* gp = g_gates + ((size_t)t * BATCH + b) * 8;
        #pragma unroll
        for (int j = 0; j < 8; j++) gp[j] = e[j] * inv;
    }
}

// ---------------------------------------------------------------------------
// K2: fp16 mma.sync expert GEMM.
// CTA tile 256(M) x 128(N) x 32(K); 8 warps 4(m)x2(n) -> 64x64 warp tiles.
// A smem [256][40] fp16 (80B rows), B smem [128][40] fp16 ([n][k]).
// 4-stage cp.async pipeline (123 KB).
// ---------------------------------------------------------------------------
#define STAGES      4
#define A_STRIDE_H  40                       // fp16 units; 80 B rows
#define B_STRIDE_H  40
#define A_BYTES_H   (256 * A_STRIDE_H * 2)   // 20480
#define B_BYTES_H   (128 * B_STRIDE_H * 2)   // 10240
#define STAGE_H     (A_BYTES_H + B_BYTES_H)  // 30720
#define SMEM_GEMM   (STAGES * STAGE_H + 512)

__global__ __launch_bounds__(256, 1) void expert_gemm_f16(const float* __restrict__ bs,
                                                          const float* __restrict__ bt)
{
    extern __shared__ char smem[];
    const uint32_t sbase = smem_u32(smem);
    float* biassm = (float*)(smem + STAGES * STAGE_H);

    const int tid  = threadIdx.x;
    const int w    = tid >> 5;
    const int lane = tid & 31;
    const int gid  = lane >> 2;     // 0..7
    const int tig  = lane & 3;      // 0..3
    const int warp_m = (w >> 1) * 64;   // 0,64,128,192
    const int warp_n = (w & 1) * 64;    // 0,64

    const int e  = blockIdx.z;
    const int n0 = blockIdx.x * 128;
    const int m0 = blockIdx.y * 256;

    const __half* W   = g_wh + (size_t)e * DM * HD;      // [n][k]
    const float* bias = (e < 4) ? bs + (size_t)e * HD : bt + (size_t)(e - 4) * HD;
    float* Y = g_y_buf + (size_t)e * BATCH * HD;

    if (tid < 128) biassm[tid] = bias[n0 + tid];

    float c[4][8][4];
    #pragma unroll
    for (int mi = 0; mi < 4; mi++)
        #pragma unroll
        for (int ni = 0; ni < 8; ni++)
            #pragma unroll
            for (int r = 0; r < 4; r++) c[mi][ni][r] = 0.f;

    // stage loader: A 256x32 fp16 (4 x 16B chunks/row), B 128x32 fp16 (4 chunks/row)
    auto load_stage = [&](int s, int kt) {
        const uint32_t ab = sbase + (uint32_t)s * STAGE_H;
        const uint32_t bb = ab + A_BYTES_H;
        const int kbase = kt * 32;
        #pragma unroll
        for (int i = 0; i < 4; i++) {               // A: 1024 chunks
            const int idx = tid + i * 256;
            const int row = idx >> 2, q = idx & 3;
            cp_async16(ab + (uint32_t)(row * 80 + q * 16),
                       g_xh + (size_t)(m0 + row) * DM + kbase + q * 8);
        }
        #pragma unroll
        for (int i = 0; i < 2; i++) {               // B: 512 chunks
            const int idx = tid + i * 256;
            const int row = idx >> 2, q = idx & 3;
            cp_async16(bb + (uint32_t)(row * 80 + q * 16),
                       W + (size_t)(n0 + row) * DM + kbase + q * 8);
        }
        cp_commit();
    };

    load_stage(0, 0);
    load_stage(1, 1);
    load_stage(2, 2);

    for (int kt = 0; kt < 32; kt++) {
        __syncthreads();                         // stage (kt-1)%4 now free
        if (kt + 3 < 32) { load_stage((kt + 3) % STAGES, kt + 3); cp_wait_group<3>(); }
        else             { cp_wait_group<0>(); }
        __syncthreads();                         // stage kt visible

        const __half* Asb = (const __half*)(smem + (kt % STAGES) * STAGE_H);
        const __half* Bsb = (const __half*)(smem + (kt % STAGES) * STAGE_H + A_BYTES_H);

        #pragma unroll
        for (int ks = 0; ks < 2; ks++) {         // two k16 slices
            const int k = ks * 16;
            uint32_t a[4][4];
            #pragma unroll
            for (int mi = 0; mi < 4; mi++) {
                const int m = warp_m + mi * 16;
                a[mi][0] = *(const uint32_t*)(Asb + (m + gid)     * A_STRIDE_H + k + tig * 2);
                a[mi][1] = *(const uint32_t*)(Asb + (m + gid + 8) * A_STRIDE_H + k + tig * 2);
                a[mi][2] = *(const uint32_t*)(Asb + (m + gid)     * A_STRIDE_H + k + tig * 2 + 8);
                a[mi][3] = *(const uint32_t*)(Asb + (m + gid + 8) * A_STRIDE_H + k + tig * 2 + 8);
            }
            uint32_t b[8][2];
            #pragma unroll
            for (int ni = 0; ni < 8; ni++) {
                const int n = warp_n + ni * 8 + gid;
                b[ni][0] = *(const uint32_t*)(Bsb + n * B_STRIDE_H + k + tig * 2);
                b[ni][1] = *(const uint32_t*)(Bsb + n * B_STRIDE_H + k + tig * 2 + 8);
            }
            #pragma unroll
            for (int mi = 0; mi < 4; mi++)
                #pragma unroll
                for (int ni = 0; ni < 8; ni++)
                    mma_f16(c[mi][ni], a[mi], b[ni]);
        }
    }

    // epilogue: bias + relu, float2 stores
    #pragma unroll
    for (int mi = 0; mi < 4; mi++) {
        #pragma unroll
        for (int ni = 0; ni < 8; ni++) {
            const int rbase = m0 + warp_m + mi * 16 + gid;
            const int col   = warp_n + ni * 8 + 2 * tig;
            const float b0 = biassm[col], b1 = biassm[col + 1];
            float2 v0, v1;
            v0.x = fmaxf(c[mi][ni][0] + b0, 0.f);
            v0.y = fmaxf(c[mi][ni][1] + b1, 0.f);
            v1.x = fmaxf(c[mi][ni][2] + b0, 0.f);
            v1.y = fmaxf(c[mi][ni][3] + b1, 0.f);
            *(float2*)(Y + (size_t)rbase * HD + n0 + col)       = v0;
            *(float2*)(Y + (size_t)(rbase + 8) * HD + n0 + col) = v1;
        }
    }
}

// ---------------------------------------------------------------------------
// K3: gated mixture
// ---------------------------------------------------------------------------
__global__ __launch_bounds__(256) void mix_kernel(float* __restrict__ out)
{
    const size_t idx = (size_t)blockIdx.x * blockDim.x + threadIdx.x;
    const int h4 = (int)(idx & 255);
    const size_t tb = idx >> 8;
    const int b = (int)(tb % BATCH);
    const int t = (int)(tb / BATCH);

    const float* gp = g_gates + ((size_t)t * BATCH + b) * 8;
    float g[8];
    #pragma unroll
    for (int j = 0; j < 8; j++) g[j] = gp[j];

    float4 acc = make_float4(0.f, 0.f, 0.f, 0.f);
    #pragma unroll
    for (int j = 0; j < 8; j++) {
        const int ei = (j < 4) ? (4 + t * 4 + j) : (j - 4);
        const float4 v = *(const float4*)(g_y_buf + ((size_t)ei * BATCH + b) * HD + (size_t)h4 * 4);
        acc.x = fmaf(g[j], v.x, acc.x);
        acc.y = fmaf(g[j], v.y, acc.y);
        acc.z = fmaf(g[j], v.z, acc.z);
        acc.w = fmaf(g[j], v.w, acc.w);
    }
    *(float4*)(out + idx * 4) = acc;
}

// ---------------------------------------------------------------------------
extern "C" void kernel_launch(void* const* d_in, const int* in_sizes, int n_in,
                              void* d_out, int out_size)
{
    (void)in_sizes; (void)n_in; (void)out_size;
    const float* x  = (const float*)d_in[0];
    const float* Ws = (const float*)d_in[1];
    const float* bs = (const float*)d_in[2];
    const float* Wt = (const float*)d_in[3];
    const float* bt = (const float*)d_in[4];
    const float* Wg = (const float*)d_in[5];
    float* out = (float*)d_out;

    cudaFuncSetAttribute(expert_gemm_f16,
                         cudaFuncAttributeMaxDynamicSharedMemorySize, SMEM_GEMM);

    {
        __half* xh = nullptr;
        cudaGetSymbolAddress((void**)&xh, g_xh);
        cvt_x<<<(unsigned)((size_t)BATCH * DM / 8 / 256), 256>>>(x, xh);
        cvt_w<<<dim3(32, 32, 16), 256>>>(Ws, Wt);
    }

    gate_kernel<<<BATCH, 96>>>(x, Wg);
    expert_gemm_f16<<<dim3(8, 32, 16), 256, SMEM_GEMM>>>(bs, bt);

    const size_t total4 = (size_t)NTASK * BATCH * (HD / 4);
    mix_kernel<<<(unsigned)(total4 / 256), 256>>>(out);
}